// round 1
// baseline (speedup 1.0000x reference)
#include <cuda_runtime.h>

#define BATCH  131072
#define TSTEPS 6
#define NV     31
#define VP     32
#define NP     16   // f32x2 pairs per padded row
#define NL     3
#define NT     128  // threads per block

typedef unsigned long long u64;

__device__ __forceinline__ u64 ffma2(u64 a, u64 b, u64 c){
    u64 d;
    asm("fma.rn.f32x2 %0, %1, %2, %3;" : "=l"(d) : "l"(a), "l"(b), "l"(c));
    return d;
}
__device__ __forceinline__ u64 pack2(float lo, float hi){
    u64 d; asm("mov.b64 %0, {%1, %2};" : "=l"(d) : "f"(lo), "f"(hi)); return d;
}
__device__ __forceinline__ void unpack2(u64 v, float& lo, float& hi){
    asm("mov.b64 {%0, %1}, %2;" : "=f"(lo), "=f"(hi) : "l"(v));
}
// tanh(x) = 1 - 2/(e^{2x}+1); ~1e-6 rel error, saturates correctly at +-inf
__device__ __forceinline__ float fast_tanh(float x){
    float e = __expf(2.0f * x);
    return 1.0f - __fdividef(2.0f, e + 1.0f);
}

__global__ void __launch_bounds__(NT)
rnn_fused(const float* __restrict__ inp,  const float* __restrict__ h0,
          const float* __restrict__ W_ih, const float* __restrict__ W_hh,
          const float* __restrict__ b_ih, const float* __restrict__ b_hh,
          const float* __restrict__ W_lin,const float* __restrict__ b_lin,
          float* __restrict__ out)
{
    // weight pair (W[l][j][2p], W[l][j][2p+1]), zero-padded to 32x32
    __shared__ __align__(16) u64   sWih[NL][VP][NP];   // 12 KB
    __shared__ __align__(16) u64   sWhh[NL][VP][NP];   // 12 KB
    __shared__ __align__(16) u64   sWlin[VP][NP];      //  4 KB
    __shared__ float sBias[NL][VP];
    __shared__ float sBlin[VP];
    // staging buffer: rows of 34 floats (136B, 8B-aligned pairs, odd u64 stride
    // -> conflict-light). Reused as per-thread h-scratch (u64[17] rows) and
    // as the softmax output staging area.
    __shared__ __align__(16) float sBuf[NT * 34];      // 17 KB

    const int tid = threadIdx.x;
    const size_t b0 = (size_t)blockIdx.x * NT;

    // ---- weight prep: pack k-pairs, pad row 31 / col 31 with zeros ----
    for (int e = tid; e < 3584; e += NT){
        float lo = 0.f, hi = 0.f;
        if (e < 1536){
            int l = e >> 9, r = e & 511, j = r >> 4, p = r & 15;
            int k0 = 2 * p;
            if (j < NV){
                const float* row = W_ih + (l * NV + j) * NV;
                lo = row[k0];
                if (k0 + 1 < NV) hi = row[k0 + 1];
            }
            sWih[l][j][p] = pack2(lo, hi);
        } else if (e < 3072){
            int e2 = e - 1536;
            int l = e2 >> 9, r = e2 & 511, j = r >> 4, p = r & 15;
            int k0 = 2 * p;
            if (j < NV){
                const float* row = W_hh + (l * NV + j) * NV;
                lo = row[k0];
                if (k0 + 1 < NV) hi = row[k0 + 1];
            }
            sWhh[l][j][p] = pack2(lo, hi);
        } else {
            int r = e - 3072, j = r >> 4, p = r & 15;
            int k0 = 2 * p;
            if (j < NV){
                const float* row = W_lin + j * NV;
                lo = row[k0];
                if (k0 + 1 < NV) hi = row[k0 + 1];
            }
            sWlin[j][p] = pack2(lo, hi);
        }
    }
    if (tid < NL * VP){
        int l = tid >> 5, j = tid & 31;
        sBias[l][j] = (j < NV) ? (b_ih[l * NV + j] + b_hh[l * NV + j]) : 0.f;
    }
    if (tid < VP) sBlin[tid] = (tid < NV) ? b_lin[tid] : 0.f;
    __syncthreads();

    // incremental (bb, v) decomposition of flat staging index (i += 128 == bb+=4, v+=4 mod 31)
    const int bb0 = tid / NV;
    const int v0  = tid - bb0 * NV;

    u64 xp[NP];
    u64 hpk[NL][NP];

    // ---- stage h0 (coalesced) and load into registers ----
    #pragma unroll
    for (int l = 0; l < NL; l++){
        const float* src = h0 + ((size_t)l * BATCH + b0) * NV;
        int bb = bb0, v = v0;
        for (int i = tid; i < NT * NV; i += NT){
            sBuf[bb * 34 + v] = src[i];
            v += 4; bb += 4;
            if (v >= NV){ v -= NV; bb++; }
        }
        sBuf[tid * 34 + NV] = 0.f;   // pad lane 31
        __syncthreads();
        #pragma unroll
        for (int p = 0; p < NP; p++)
            hpk[l][p] = *reinterpret_cast<const u64*>(&sBuf[tid * 34 + 2 * p]);
        __syncthreads();
    }

    u64* myh = reinterpret_cast<u64*>(&sBuf[tid * 34]);  // thread-private scratch row

    for (int t = 0; t < TSTEPS; t++){
        // ---- stage x_t (coalesced gather of strided 124B rows) ----
        {
            const float* src = inp + (b0 * TSTEPS + t) * NV;
            int bb = bb0, v = v0;
            for (int i = tid; i < NT * NV; i += NT){
                sBuf[bb * 34 + v] = src[(size_t)bb * (TSTEPS * NV) + v];
                v += 4; bb += 4;
                if (v >= NV){ v -= NV; bb++; }
            }
            sBuf[tid * 34 + NV] = 0.f;
        }
        __syncthreads();
        #pragma unroll
        for (int p = 0; p < NP; p++)
            xp[p] = *reinterpret_cast<const u64*>(&sBuf[tid * 34 + 2 * p]);

        // ---- 3 RNN layers, h state in registers ----
        #pragma unroll
        for (int l = 0; l < NL; l++){
            #pragma unroll 1
            for (int jp = 0; jp < NP; jp++){
                const ulonglong2* w0 = reinterpret_cast<const ulonglong2*>(&sWih[l][2*jp  ][0]);
                const ulonglong2* w1 = reinterpret_cast<const ulonglong2*>(&sWih[l][2*jp+1][0]);
                const ulonglong2* u0 = reinterpret_cast<const ulonglong2*>(&sWhh[l][2*jp  ][0]);
                const ulonglong2* u1 = reinterpret_cast<const ulonglong2*>(&sWhh[l][2*jp+1][0]);
                u64 a0 = 0ull, a1 = 0ull, c0 = 0ull, c1 = 0ull;  // 4 chains, ILP=4
                #pragma unroll
                for (int q = 0; q < NP/2; q++){
                    ulonglong2 wa = w0[q], wb = w1[q];
                    a0 = ffma2(wa.x, xp[2*q],   a0);
                    c0 = ffma2(wa.y, xp[2*q+1], c0);
                    a1 = ffma2(wb.x, xp[2*q],   a1);
                    c1 = ffma2(wb.y, xp[2*q+1], c1);
                }
                #pragma unroll
                for (int q = 0; q < NP/2; q++){
                    ulonglong2 wa = u0[q], wb = u1[q];
                    a0 = ffma2(wa.x, hpk[l][2*q],   a0);
                    c0 = ffma2(wa.y, hpk[l][2*q+1], c0);
                    a1 = ffma2(wb.x, hpk[l][2*q],   a1);
                    c1 = ffma2(wb.y, hpk[l][2*q+1], c1);
                }
                float x0,x1,x2,x3,x4,x5,x6,x7;
                unpack2(a0,x0,x1); unpack2(c0,x2,x3);
                unpack2(a1,x4,x5); unpack2(c1,x6,x7);
                float y0 = fast_tanh(((x0+x2)+(x1+x3)) + sBias[l][2*jp]);
                float y1 = fast_tanh(((x4+x6)+(x5+x7)) + sBias[l][2*jp+1]);
                myh[jp] = pack2(y0, y1);   // row-31 pad computes tanh(0)=0 -> pad lane stays 0
            }
            #pragma unroll
            for (int p = 0; p < NP; p++){
                u64 v = myh[p];
                xp[p]     = v;   // next layer's input
                hpk[l][p] = v;   // this layer's carried state
            }
        }
        __syncthreads();  // all threads done re-reading their scratch rows before next stage
    }

    // ---- final linear + tanh ----
    float y[VP];
    #pragma unroll
    for (int jp = 0; jp < NP; jp++){
        const ulonglong2* w0 = reinterpret_cast<const ulonglong2*>(&sWlin[2*jp  ][0]);
        const ulonglong2* w1 = reinterpret_cast<const ulonglong2*>(&sWlin[2*jp+1][0]);
        u64 a0 = 0ull, a1 = 0ull, c0 = 0ull, c1 = 0ull;
        #pragma unroll
        for (int q = 0; q < NP/2; q++){
            ulonglong2 wa = w0[q], wb = w1[q];
            a0 = ffma2(wa.x, xp[2*q],   a0);
            c0 = ffma2(wa.y, xp[2*q+1], c0);
            a1 = ffma2(wb.x, xp[2*q],   a1);
            c1 = ffma2(wb.y, xp[2*q+1], c1);
        }
        float x0,x1,x2,x3,x4,x5,x6,x7;
        unpack2(a0,x0,x1); unpack2(c0,x2,x3);
        unpack2(a1,x4,x5); unpack2(c1,x6,x7);
        y[2*jp  ] = fast_tanh(((x0+x2)+(x1+x3)) + sBlin[2*jp]);
        y[2*jp+1] = fast_tanh(((x4+x6)+(x5+x7)) + sBlin[2*jp+1]);
    }

    // ---- softmax over the 31 real lanes ----
    float m = y[0];
    #pragma unroll
    for (int j = 1; j < NV; j++) m = fmaxf(m, y[j]);
    float s = 0.f;
    #pragma unroll
    for (int j = 0; j < NV; j++){ y[j] = __expf(y[j] - m); s += y[j]; }
    float inv = __fdividef(1.0f, s);

    // ---- coalesced output via shared ----
    #pragma unroll
    for (int j = 0; j < NV; j++) sBuf[tid * NV + j] = y[j] * inv;  // disjoint regions per thread
    __syncthreads();
    for (int i = tid; i < NT * NV; i += NT)
        out[b0 * NV + i] = sBuf[i];
}

extern "C" void kernel_launch(void* const* d_in, const int* in_sizes, int n_in,
                              void* d_out, int out_size)
{
    const float* inp   = (const float*)d_in[0];
    const float* h0    = (const float*)d_in[1];
    const float* W_ih  = (const float*)d_in[2];
    const float* W_hh  = (const float*)d_in[3];
    const float* b_ih  = (const float*)d_in[4];
    const float* b_hh  = (const float*)d_in[5];
    const float* W_lin = (const float*)d_in[6];
    const float* b_lin = (const float*)d_in[7];
    float* out = (float*)d_out;

    rnn_fused<<<BATCH / NT, NT>>>(inp, h0, W_ih, W_hh, b_ih, b_hh, W_lin, b_lin, out);
}

// round 3
// speedup vs baseline: 1.0958x; 1.0958x over previous
#include <cuda_runtime.h>
#include <cstdint>

#define BATCH  131072
#define TSTEPS 6
#define NV     31
#define NL     3
#define NT     128
#define MPW    32           // batch rows per warp
#define RSTRIDE 36          // scratch row stride in floats (conflict-free frag reads)

// shared layout (in floats)
#define W_FLOATS  (7*16*32*2)          // 7 matrices, fragment order, f32: 28672 B
#define BIAS_OFF  (W_FLOATS)           // 4 sets x 32
#define BUF_OFF   (W_FLOATS + 128)
#define BUF_SIZE  (MPW * RSTRIDE)      // 1152 floats
#define SMEM_FLOATS (BUF_OFF + 4 * 4 * BUF_SIZE)
#define SMEM_BYTES  (SMEM_FLOATS * 4)  // 102912 B -> 2 CTAs/SM

__device__ __forceinline__ uint32_t f2tf(float x){
    uint32_t r; asm("cvt.rna.tf32.f32 %0, %1;" : "=r"(r) : "f"(x)); return r;
}
__device__ __forceinline__ void mma_tf32(float& d0, float& d1, float& d2, float& d3,
                                         uint32_t a0, uint32_t a1, uint32_t a2, uint32_t a3,
                                         uint32_t b0, uint32_t b1){
    asm volatile("mma.sync.aligned.m16n8k8.row.col.f32.tf32.tf32.f32 "
                 "{%0,%1,%2,%3}, {%4,%5,%6,%7}, {%8,%9}, {%0,%1,%2,%3};"
                 : "+f"(d0), "+f"(d1), "+f"(d2), "+f"(d3)
                 : "r"(a0), "r"(a1), "r"(a2), "r"(a3), "r"(b0), "r"(b1));
}
// tanh(x) = 1 - 2/(e^{2x}+1): 2 MUFU, ~1e-7 rel err, correct saturation
__device__ __forceinline__ float fast_tanh(float x){
    float e = __expf(2.0f * x);
    return 1.0f - __fdividef(2.0f, e + 1.0f);
}

// D[2][4][4] += src[32,32] (f32, stride RSTRIDE) x W_m^T via 3-product tf32 split.
// m16n8k8 frags: A a0(q,r) a1(q+8,r) a2(q,r+4) a3(q+8,r+4); B b0(r,q) b1(r+4,q);
// D c0(q,2r) c1(q,2r+1) c2(q+8,2r) c3(q+8,2r+1).
__device__ __forceinline__ void accum_mm(float D[2][4][4], const float* __restrict__ src,
                                         const float* __restrict__ wf, int q, int r, int lane){
    #pragma unroll
    for (int kt = 0; kt < 4; kt++){
        uint32_t bh[4][2], bl[4][2];
        #pragma unroll
        for (int nt = 0; nt < 4; nt++){
            float2 w = *(const float2*)(wf + (size_t)((kt*4 + nt)*32 + lane)*2);
            uint32_t h0 = f2tf(w.x); bl[nt][0] = f2tf(w.x - __uint_as_float(h0));
            uint32_t h1 = f2tf(w.y); bl[nt][1] = f2tf(w.y - __uint_as_float(h1));
            bh[nt][0] = h0; bh[nt][1] = h1;
        }
        #pragma unroll
        for (int mt = 0; mt < 2; mt++){
            const float* s0 = src + (mt*16 + q)*RSTRIDE + kt*8 + r;
            float a00 = s0[0],          a02 = s0[4];
            float a01 = s0[8*RSTRIDE],  a03 = s0[8*RSTRIDE + 4];
            uint32_t ah0 = f2tf(a00), ah1 = f2tf(a01), ah2 = f2tf(a02), ah3 = f2tf(a03);
            uint32_t al0 = f2tf(a00 - __uint_as_float(ah0));
            uint32_t al1 = f2tf(a01 - __uint_as_float(ah1));
            uint32_t al2 = f2tf(a02 - __uint_as_float(ah2));
            uint32_t al3 = f2tf(a03 - __uint_as_float(ah3));
            #pragma unroll
            for (int nt = 0; nt < 4; nt++){
                mma_tf32(D[mt][nt][0], D[mt][nt][1], D[mt][nt][2], D[mt][nt][3],
                         ah0, ah1, ah2, ah3, bh[nt][0], bh[nt][1]);
                mma_tf32(D[mt][nt][0], D[mt][nt][1], D[mt][nt][2], D[mt][nt][3],
                         ah0, ah1, ah2, ah3, bl[nt][0], bl[nt][1]);
                mma_tf32(D[mt][nt][0], D[mt][nt][1], D[mt][nt][2], D[mt][nt][3],
                         al0, al1, al2, al3, bh[nt][0], bh[nt][1]);
            }
        }
    }
}

extern __shared__ float smem[];

__global__ void __launch_bounds__(NT, 2)
rnn_hmma(const float* __restrict__ inp,  const float* __restrict__ h0,
         const float* __restrict__ W_ih, const float* __restrict__ W_hh,
         const float* __restrict__ b_ih, const float* __restrict__ b_hh,
         const float* __restrict__ W_lin,const float* __restrict__ b_lin,
         float* __restrict__ out)
{
    const int tid  = threadIdx.x;
    const int warp = tid >> 5;
    const int lane = tid & 31;
    const int q = lane >> 2, r = lane & 3;
    const size_t b0w = (size_t)blockIdx.x * NT + warp * MPW;

    float* sW    = smem;
    float* sBias = smem + BIAS_OFF;
    float* xbuf  = smem + BUF_OFF + warp * 4 * BUF_SIZE;
    float* hbuf0 = xbuf + BUF_SIZE;   // hbuf[l] = hbuf0 + l*BUF_SIZE

    // ---- one-time weight prep: f32, B-fragment order, zero-padded to 32x32 ----
    // idx bits: s=b0, lane=b1..5, nt=b6..7, kt=b8..9, m=b10..12
    for (int idx = tid; idx < 7*1024; idx += NT){
        int s  = idx & 1;
        int ln = (idx >> 1) & 31;
        int nt = (idx >> 6) & 3;
        int kt = (idx >> 8) & 3;
        int m  = idx >> 10;
        int jj = nt*8 + (ln >> 2);
        int kk = kt*8 + (ln & 3) + 4*s;
        const float* srcm = (m < 3) ? (W_ih + m*NV*NV)
                          : (m < 6) ? (W_hh + (m-3)*NV*NV)
                                    : W_lin;
        sW[idx] = (jj < NV && kk < NV) ? srcm[jj*NV + kk] : 0.0f;
    }
    {   // bias: sets 0..2 = b_ih+b_hh per layer, set 3 = b_lin
        int l = tid >> 5, j = tid & 31;
        float v = 0.0f;
        if (j < NV) v = (l < 3) ? (b_ih[l*NV + j] + b_hh[l*NV + j]) : b_lin[j];
        sBias[l*32 + j] = v;
    }
    __syncthreads();
    // ---- from here on, each warp is fully independent ----

    // stage h0 (coalesced, per-warp)
    #pragma unroll
    for (int l = 0; l < NL; l++){
        float* hb = hbuf0 + l * BUF_SIZE;
        const float* src = h0 + ((size_t)l * BATCH + b0w) * NV;
        for (int i = lane; i < MPW*NV; i += 32)
            hb[(i/NV)*RSTRIDE + (i%NV)] = src[i];
        hb[lane*RSTRIDE + NV] = 0.0f;     // pad col 31
    }
    xbuf[lane*RSTRIDE + NV] = 0.0f;

    float D[2][4][4];

    #pragma unroll 1
    for (int t = 0; t < TSTEPS; t++){
        // stage x_t (per-warp, coalesced within rows)
        {
            const float* src = inp;
            for (int i = lane; i < MPW*NV; i += 32){
                int row = i / NV, v = i - row*NV;
                xbuf[row*RSTRIDE + v] = src[((b0w + row)*TSTEPS + t)*NV + v];
            }
        }
        __syncwarp();

        const float* xsrc = xbuf;
        #pragma unroll 1
        for (int l = 0; l < NL; l++){
            float* hb = hbuf0 + l * BUF_SIZE;
            // init D from combined bias
            #pragma unroll
            for (int nt = 0; nt < 4; nt++){
                float bA = sBias[l*32 + nt*8 + 2*r];
                float bB = sBias[l*32 + nt*8 + 2*r + 1];
                D[0][nt][0] = bA; D[0][nt][1] = bB; D[0][nt][2] = bA; D[0][nt][3] = bB;
                D[1][nt][0] = bA; D[1][nt][1] = bB; D[1][nt][2] = bA; D[1][nt][3] = bB;
            }
            accum_mm(D, xsrc, sW + (size_t)l*1024,       q, r, lane);   // x @ Wih^T
            accum_mm(D, hb,   sW + (size_t)(3+l)*1024,   q, r, lane);   // h @ Whh^T
            __syncwarp();
            // epilogue: tanh -> h scratch
            #pragma unroll
            for (int mt = 0; mt < 2; mt++){
                #pragma unroll
                for (int nt = 0; nt < 4; nt++){
                    float y0 = fast_tanh(D[mt][nt][0]);
                    float y1 = fast_tanh(D[mt][nt][1]);
                    float y2 = fast_tanh(D[mt][nt][2]);
                    float y3 = fast_tanh(D[mt][nt][3]);
                    float* p = hb + (mt*16 + q)*RSTRIDE + nt*8 + 2*r;
                    *(float2*)p               = make_float2(y0, y1);
                    *(float2*)(p + 8*RSTRIDE) = make_float2(y2, y3);
                }
            }
            __syncwarp();
            xsrc = hb;   // next layer's input
        }
    }

    // ---- final linear + tanh ----
    #pragma unroll
    for (int nt = 0; nt < 4; nt++){
        float bA = sBias[3*32 + nt*8 + 2*r];
        float bB = sBias[3*32 + nt*8 + 2*r + 1];
        D[0][nt][0] = bA; D[0][nt][1] = bB; D[0][nt][2] = bA; D[0][nt][3] = bB;
        D[1][nt][0] = bA; D[1][nt][1] = bB; D[1][nt][2] = bA; D[1][nt][3] = bB;
    }
    accum_mm(D, hbuf0 + 2*BUF_SIZE, sW + (size_t)6*1024, q, r, lane);
    #pragma unroll
    for (int mt = 0; mt < 2; mt++)
        #pragma unroll
        for (int nt = 0; nt < 4; nt++)
            #pragma unroll
            for (int i = 0; i < 4; i++)
                D[mt][nt][i] = fast_tanh(D[mt][nt][i]);
    // mask pad col 31 (nt==3, 2r+1==7 -> r==3, regs 1 and 3)
    if (r == 3){ D[0][3][1] = -3.0e38f; D[0][3][3] = -3.0e38f;
                 D[1][3][1] = -3.0e38f; D[1][3][3] = -3.0e38f; }

    // ---- softmax per row (rows live across the 4 lanes of a quad) ----
    float mx[2][2], sum[2][2];
    #pragma unroll
    for (int mt = 0; mt < 2; mt++)
        #pragma unroll
        for (int h = 0; h < 2; h++){
            float m = -3.0e38f;
            #pragma unroll
            for (int nt = 0; nt < 4; nt++)
                m = fmaxf(m, fmaxf(D[mt][nt][2*h], D[mt][nt][2*h + 1]));
            m = fmaxf(m, __shfl_xor_sync(0xffffffffu, m, 1));
            m = fmaxf(m, __shfl_xor_sync(0xffffffffu, m, 2));
            mx[mt][h] = m;
            float s = 0.0f;
            #pragma unroll
            for (int nt = 0; nt < 4; nt++){
                float e0 = __expf(D[mt][nt][2*h]     - m);
                float e1 = __expf(D[mt][nt][2*h + 1] - m);
                D[mt][nt][2*h] = e0; D[mt][nt][2*h + 1] = e1;
                s += e0 + e1;
            }
            s += __shfl_xor_sync(0xffffffffu, s, 1);
            s += __shfl_xor_sync(0xffffffffu, s, 2);
            sum[mt][h] = __fdividef(1.0f, s);
        }

    // scale + stage to xbuf, then coalesced store
    #pragma unroll
    for (int mt = 0; mt < 2; mt++)
        #pragma unroll
        for (int nt = 0; nt < 4; nt++){
            float* p = xbuf + (mt*16 + q)*RSTRIDE + nt*8 + 2*r;
            *(float2*)p               = make_float2(D[mt][nt][0]*sum[mt][0], D[mt][nt][1]*sum[mt][0]);
            *(float2*)(p + 8*RSTRIDE) = make_float2(D[mt][nt][2]*sum[mt][1], D[mt][nt][3]*sum[mt][1]);
        }
    __syncwarp();
    for (int i = lane; i < MPW*NV; i += 32)
        out[b0w*NV + i] = xbuf[(i/NV)*RSTRIDE + (i%NV)];
}

extern "C" void kernel_launch(void* const* d_in, const int* in_sizes, int n_in,
                              void* d_out, int out_size)
{
    const float* inp   = (const float*)d_in[0];
    const float* h0    = (const float*)d_in[1];
    const float* W_ih  = (const float*)d_in[2];
    const float* W_hh  = (const float*)d_in[3];
    const float* b_ih  = (const float*)d_in[4];
    const float* b_hh  = (const float*)d_in[5];
    const float* W_lin = (const float*)d_in[6];
    const float* b_lin = (const float*)d_in[7];
    float* out = (float*)d_out;

    cudaFuncSetAttribute(rnn_hmma, cudaFuncAttributeMaxDynamicSharedMemorySize, SMEM_BYTES);
    rnn_hmma<<<BATCH / NT, NT, SMEM_BYTES>>>(inp, h0, W_ih, W_hh, b_ih, b_hh,
                                             W_lin, b_lin, out);
}

// round 5
// speedup vs baseline: 1.1482x; 1.0478x over previous
#include <cuda_runtime.h>
#include <cuda_fp16.h>
#include <cstdint>

#define BATCH  131072
#define TSTEPS 6
#define NV     31
#define NL     3
#define NT     128
#define MPW    32
#define RS     34          // row stride in u32 (even -> aligned u64, odd/32 mix ok)
#define BUFU   (32 * RS)   // 1088 u32 per buffer

// shared layout in u32 units
#define W_U32    7168      // 7 matrices x 1024 u32 (B-frag order, f16 hi/lo)
#define BIAS_OFF 7168      // 128 f32
#define BUF_OFF  7296
#define SMEM_U32 (BUF_OFF + 16 * BUFU)      // 24704 u32 = 98816 B -> 2 CTAs/SM

__device__ __forceinline__ void mma_f16(float* D, uint32_t a0, uint32_t a1,
                                        uint32_t a2, uint32_t a3,
                                        uint32_t b0, uint32_t b1){
    asm volatile("mma.sync.aligned.m16n8k16.row.col.f32.f16.f16.f32 "
                 "{%0,%1,%2,%3}, {%4,%5,%6,%7}, {%8,%9}, {%0,%1,%2,%3};"
                 : "+f"(D[0]), "+f"(D[1]), "+f"(D[2]), "+f"(D[3])
                 : "r"(a0), "r"(a1), "r"(a2), "r"(a3), "r"(b0), "r"(b1));
}
__device__ __forceinline__ float fast_tanh(float x){
    float e = __expf(2.0f * x);
    return 1.0f - __fdividef(2.0f, e + 1.0f);
}
__device__ __forceinline__ uint32_t h2u(__half2 h){ return *(uint32_t*)&h; }

// write one row's 8 values (colpairs t, t+4, t+8, t+12) as hi/lo f16x2
__device__ __forceinline__ void store_split_row(uint32_t* rowp, int t,
                                                float2 v0, float2 v1,
                                                float2 v2, float2 v3){
    __half2 h0 = __floats2half2_rn(v0.x, v0.y);
    __half2 h1 = __floats2half2_rn(v1.x, v1.y);
    __half2 h2 = __floats2half2_rn(v2.x, v2.y);
    __half2 h3 = __floats2half2_rn(v3.x, v3.y);
    float2 f0 = __half22float2(h0), f1 = __half22float2(h1);
    float2 f2 = __half22float2(h2), f3 = __half22float2(h3);
    __half2 l0 = __floats2half2_rn(v0.x - f0.x, v0.y - f0.y);
    __half2 l1 = __floats2half2_rn(v1.x - f1.x, v1.y - f1.y);
    __half2 l2 = __floats2half2_rn(v2.x - f2.x, v2.y - f2.y);
    __half2 l3 = __floats2half2_rn(v3.x - f3.x, v3.y - f3.y);
    *(uint2*)(rowp + 2*t)      = make_uint2(h2u(h0), h2u(h1));
    *(uint2*)(rowp + 8 + 2*t)  = make_uint2(h2u(h2), h2u(h3));
    *(uint2*)(rowp + 16 + 2*t) = make_uint2(h2u(l0), h2u(l1));
    *(uint2*)(rowp + 24 + 2*t) = make_uint2(h2u(l2), h2u(l3));
}

// D[2][4][4] += src(32x32 split-f16 buffer) x W_m^T, 3-product f16 split
__device__ __forceinline__ void accum_mm(float D[2][4][4],
                                         const uint32_t* __restrict__ buf,
                                         const uint32_t* __restrict__ wm,
                                         int g, int t, int lane){
    #pragma unroll
    for (int kt = 0; kt < 2; kt++){
        uint4 wv[4];
        #pragma unroll
        for (int nt = 0; nt < 4; nt++)
            wv[nt] = *(const uint4*)&wm[((kt*4 + nt)*32 + lane)*4];
        #pragma unroll
        for (int mt = 0; mt < 2; mt++){
            int r0 = (mt*16 + g)*RS + kt*8 + 2*t;
            uint2 ah0 = *(const uint2*)&buf[r0];            // a0, a2 hi
            uint2 ah1 = *(const uint2*)&buf[r0 + 8*RS];     // a1, a3 hi
            uint2 al0 = *(const uint2*)&buf[r0 + 16];       // a0, a2 lo
            uint2 al1 = *(const uint2*)&buf[r0 + 8*RS + 16];// a1, a3 lo
            #pragma unroll
            for (int nt = 0; nt < 4; nt++){
                mma_f16(D[mt][nt], ah0.x, ah1.x, ah0.y, ah1.y, wv[nt].x, wv[nt].y);
                mma_f16(D[mt][nt], ah0.x, ah1.x, ah0.y, ah1.y, wv[nt].z, wv[nt].w);
                mma_f16(D[mt][nt], al0.x, al1.x, al0.y, al1.y, wv[nt].x, wv[nt].y);
            }
        }
    }
}

// read f32-staged rows (stride RS floats), split, write split format in place
__device__ __forceinline__ void split_buffer(uint32_t* buf, int g, int t){
    float* f = (float*)buf;
    float2 v[4][4];
    #pragma unroll
    for (int m4 = 0; m4 < 4; m4++){
        int row = g + 8*m4;
        v[m4][0] = *(float2*)&f[row*RS + 2*t];
        v[m4][1] = *(float2*)&f[row*RS + 2*t + 8];
        v[m4][2] = *(float2*)&f[row*RS + 2*t + 16];
        v[m4][3] = *(float2*)&f[row*RS + 2*t + 24];
    }
    __syncwarp();
    #pragma unroll
    for (int m4 = 0; m4 < 4; m4++)
        store_split_row(buf + (g + 8*m4)*RS, t, v[m4][0], v[m4][1], v[m4][2], v[m4][3]);
    __syncwarp();
}

extern __shared__ uint32_t smem[];

__global__ void __launch_bounds__(NT, 2)
rnn_hmma16(const float* __restrict__ inp,  const float* __restrict__ h0,
           const float* __restrict__ W_ih, const float* __restrict__ W_hh,
           const float* __restrict__ b_ih, const float* __restrict__ b_hh,
           const float* __restrict__ W_lin,const float* __restrict__ b_lin,
           float* __restrict__ out)
{
    const int tid  = threadIdx.x;
    const int warp = tid >> 5;
    const int lane = tid & 31;
    const int g = lane >> 2, t = lane & 3;
    const size_t b0w = (size_t)blockIdx.x * NT + warp * MPW;

    uint32_t* sW    = smem;
    float*    sBias = (float*)(smem + BIAS_OFF);
    uint32_t* xb    = smem + BUF_OFF + warp * 4 * BUFU;
    uint32_t* hb0   = xb + BUFU;        // hb(l) = hb0 + l*BUFU

    // ---- one-time weight pack: f16 hi/lo in B-fragment order ----
    // idx = (((m*2+kt)*4+nt)*32+lane)*4 + s ; s: 0=b0hi 1=b1hi 2=b0lo 3=b1lo
    for (int idx = tid; idx < 7*1024; idx += NT){
        int s  = idx & 3;
        int ln = (idx >> 2) & 31;
        int nt = (idx >> 7) & 3;
        int kt = (idx >> 9) & 1;
        int m  = idx >> 10;
        int gg = ln >> 2, tt = ln & 3;
        int j = nt*8 + gg;
        int k = kt*16 + 2*tt + (s & 1)*8;
        const float* srcm = (m < 3) ? (W_ih + m*NV*NV)
                          : (m < 6) ? (W_hh + (m-3)*NV*NV)
                                    : W_lin;
        float v0 = (j < NV && k   < NV) ? srcm[j*NV + k]   : 0.0f;
        float v1 = (j < NV && k+1 < NV) ? srcm[j*NV + k+1] : 0.0f;
        __half2 hi = __floats2half2_rn(v0, v1);
        if (s >> 1){
            float2 hf = __half22float2(hi);
            __half2 lo = __floats2half2_rn(v0 - hf.x, v1 - hf.y);
            sW[idx] = h2u(lo);
        } else {
            sW[idx] = h2u(hi);
        }
    }
    {   // bias sets: 0..2 = b_ih+b_hh, 3 = b_lin
        int l = tid >> 5, j = tid & 31;
        float v = 0.0f;
        if (j < NV) v = (l < 3) ? (b_ih[l*NV + j] + b_hh[l*NV + j]) : b_lin[j];
        sBias[l*32 + j] = v;
    }
    __syncthreads();
    // ---- warps fully independent from here ----

    // stage h0 -> split buffers
    for (int l = 0; l < NL; l++){
        uint32_t* hb = hb0 + l * BUFU;
        float* f = (float*)hb;
        const float* src = h0 + ((size_t)l * BATCH + b0w) * NV;
        for (int i = lane; i < MPW*NV; i += 32)
            f[(i/NV)*RS + (i%NV)] = src[i];
        f[lane*RS + NV] = 0.0f;
        __syncwarp();
        split_buffer(hb, g, t);
    }

    float D[2][4][4];

    #pragma unroll 1
    for (int ts = 0; ts < TSTEPS; ts++){
        // stage x_t -> split buffer
        {
            float* f = (float*)xb;
            for (int i = lane; i < MPW*NV; i += 32){
                int row = i / NV, v = i - row*NV;
                f[row*RS + v] = inp[((b0w + row)*TSTEPS + ts)*NV + v];
            }
            f[lane*RS + NV] = 0.0f;
            __syncwarp();
            split_buffer(xb, g, t);
        }

        const uint32_t* xsrc = xb;
        #pragma unroll 1
        for (int l = 0; l < NL; l++){
            uint32_t* hb = hb0 + l * BUFU;
            #pragma unroll
            for (int nt = 0; nt < 4; nt++){
                float bA = sBias[l*32 + nt*8 + 2*t];
                float bB = sBias[l*32 + nt*8 + 2*t + 1];
                D[0][nt][0] = bA; D[0][nt][1] = bB; D[0][nt][2] = bA; D[0][nt][3] = bB;
                D[1][nt][0] = bA; D[1][nt][1] = bB; D[1][nt][2] = bA; D[1][nt][3] = bB;
            }
            accum_mm(D, xsrc, sW + l*1024,     g, t, lane);   // x @ Wih^T
            accum_mm(D, hb,   sW + (3+l)*1024, g, t, lane);   // h @ Whh^T
            __syncwarp();
            #pragma unroll
            for (int mt = 0; mt < 2; mt++)
                #pragma unroll
                for (int h = 0; h < 2; h++){
                    int row = g + 8*h + 16*mt;
                    float2 v0 = make_float2(fast_tanh(D[mt][0][2*h]), fast_tanh(D[mt][0][2*h+1]));
                    float2 v1 = make_float2(fast_tanh(D[mt][1][2*h]), fast_tanh(D[mt][1][2*h+1]));
                    float2 v2 = make_float2(fast_tanh(D[mt][2][2*h]), fast_tanh(D[mt][2][2*h+1]));
                    float2 v3 = make_float2(fast_tanh(D[mt][3][2*h]), fast_tanh(D[mt][3][2*h+1]));
                    store_split_row(hb + row*RS, t, v0, v1, v2, v3);
                }
            __syncwarp();
            xsrc = hb;
        }
    }

    // ---- final linear + tanh ----
    #pragma unroll
    for (int nt = 0; nt < 4; nt++){
        float bA = sBias[3*32 + nt*8 + 2*t];
        float bB = sBias[3*32 + nt*8 + 2*t + 1];
        D[0][nt][0] = bA; D[0][nt][1] = bB; D[0][nt][2] = bA; D[0][nt][3] = bB;
        D[1][nt][0] = bA; D[1][nt][1] = bB; D[1][nt][2] = bA; D[1][nt][3] = bB;
    }
    accum_mm(D, hb0 + 2*BUFU, sW + 6*1024, g, t, lane);
    #pragma unroll
    for (int mt = 0; mt < 2; mt++)
        #pragma unroll
        for (int nt = 0; nt < 4; nt++)
            #pragma unroll
            for (int i = 0; i < 4; i++)
                D[mt][nt][i] = fast_tanh(D[mt][nt][i]);
    if (t == 3){ D[0][3][1] = -3.0e38f; D[0][3][3] = -3.0e38f;
                 D[1][3][1] = -3.0e38f; D[1][3][3] = -3.0e38f; }

    // ---- softmax per row (across quad lanes) ----
    float* fs = (float*)xb;
    #pragma unroll
    for (int mt = 0; mt < 2; mt++)
        #pragma unroll
        for (int h = 0; h < 2; h++){
            float m = -3.0e38f;
            #pragma unroll
            for (int nt = 0; nt < 4; nt++)
                m = fmaxf(m, fmaxf(D[mt][nt][2*h], D[mt][nt][2*h+1]));
            m = fmaxf(m, __shfl_xor_sync(0xffffffffu, m, 1));
            m = fmaxf(m, __shfl_xor_sync(0xffffffffu, m, 2));
            float s = 0.0f;
            #pragma unroll
            for (int nt = 0; nt < 4; nt++){
                float e0 = __expf(D[mt][nt][2*h]   - m);
                float e1 = __expf(D[mt][nt][2*h+1] - m);
                D[mt][nt][2*h] = e0; D[mt][nt][2*h+1] = e1;
                s += e0 + e1;
            }
            s += __shfl_xor_sync(0xffffffffu, s, 1);
            s += __shfl_xor_sync(0xffffffffu, s, 2);
            float inv = __fdividef(1.0f, s);
            int row = g + 8*h + 16*mt;
            #pragma unroll
            for (int nt = 0; nt < 4; nt++)
                *(float2*)&fs[row*RS + nt*8 + 2*t] =
                    make_float2(D[mt][nt][2*h]*inv, D[mt][nt][2*h+1]*inv);
        }
    __syncwarp();
    for (int i = lane; i < MPW*NV; i += 32)
        out[b0w*NV + i] = fs[(i/NV)*RS + (i%NV)];
}

extern "C" void kernel_launch(void* const* d_in, const int* in_sizes, int n_in,
                              void* d_out, int out_size)
{
    const float* inp   = (const float*)d_in[0];
    const float* h0    = (const float*)d_in[1];
    const float* W_ih  = (const float*)d_in[2];
    const float* W_hh  = (const float*)d_in[3];
    const float* b_ih  = (const float*)d_in[4];
    const float* b_hh  = (const float*)d_in[5];
    const float* W_lin = (const float*)d_in[6];
    const float* b_lin = (const float*)d_in[7];
    float* out = (float*)d_out;

    cudaFuncSetAttribute(rnn_hmma16, cudaFuncAttributeMaxDynamicSharedMemorySize,
                         SMEM_U32 * 4);
    rnn_hmma16<<<BATCH / NT, NT, SMEM_U32 * 4>>>(inp, h0, W_ih, W_hh, b_ih, b_hh,
                                                 W_lin, b_lin, out);
}

// round 7
// speedup vs baseline: 2.7418x; 2.3879x over previous
#include <cuda_runtime.h>
#include <cuda_fp16.h>
#include <cstdint>

#define BATCH  131072
#define TSTEPS 6
#define NV     31
#define NL     3
#define NT     128

__device__ __forceinline__ void mma_f16(float* D, uint32_t a0, uint32_t a1,
                                        uint32_t a2, uint32_t a3,
                                        uint32_t b0, uint32_t b1){
    asm volatile("mma.sync.aligned.m16n8k16.row.col.f32.f16.f16.f32 "
                 "{%0,%1,%2,%3}, {%4,%5,%6,%7}, {%8,%9}, {%0,%1,%2,%3};"
                 : "+f"(D[0]), "+f"(D[1]), "+f"(D[2]), "+f"(D[3])
                 : "r"(a0), "r"(a1), "r"(a2), "r"(a3), "r"(b0), "r"(b1));
}
__device__ __forceinline__ float fast_tanh(float x){
    float e = __expf(2.0f * x);
    return 1.0f - __fdividef(2.0f, e + 1.0f);
}
__device__ __forceinline__ uint32_t h2u(__half2 h){ return *(uint32_t*)&h; }
// pack (x,y) -> hi f16x2 and residual lo f16x2
__device__ __forceinline__ void split2(float x, float y, uint32_t& hi, uint32_t& lo){
    __half2 h = __floats2half2_rn(x, y);
    float2 f = __half22float2(h);
    hi = h2u(h);
    lo = h2u(__floats2half2_rn(x - f.x, y - f.y));
}

// D[2][4][4] += A(frags) x W^T, 3-product f16 split, B from shared
__device__ __forceinline__ void accum_frag(float D[2][4][4],
                                           const uint32_t (&A)[2][2][4],
                                           const uint32_t (&L)[2][2][4],
                                           const uint32_t* __restrict__ wm, int lane){
    #pragma unroll
    for (int kt = 0; kt < 2; kt++){
        uint4 wv[4];
        #pragma unroll
        for (int nt = 0; nt < 4; nt++)
            wv[nt] = ((const uint4*)wm)[(kt*4 + nt)*32 + lane];
        #pragma unroll
        for (int mt = 0; mt < 2; mt++)
            #pragma unroll
            for (int nt = 0; nt < 4; nt++){
                mma_f16(D[mt][nt], A[mt][kt][0], A[mt][kt][1], A[mt][kt][2], A[mt][kt][3],
                        wv[nt].x, wv[nt].y);
                mma_f16(D[mt][nt], A[mt][kt][0], A[mt][kt][1], A[mt][kt][2], A[mt][kt][3],
                        wv[nt].z, wv[nt].w);
                mma_f16(D[mt][nt], L[mt][kt][0], L[mt][kt][1], L[mt][kt][2], L[mt][kt][3],
                        wv[nt].x, wv[nt].y);
            }
    }
}

__global__ void __launch_bounds__(NT, 3)
rnn_reg(const float* __restrict__ inp,  const float* __restrict__ h0,
        const float* __restrict__ W_ih, const float* __restrict__ W_hh,
        const float* __restrict__ b_ih, const float* __restrict__ b_hh,
        const float* __restrict__ W_lin,const float* __restrict__ b_lin,
        float* __restrict__ out)
{
    __shared__ __align__(16) uint32_t sW[7*1024];   // 7 matrices, B-frag order, f16 hi/lo
    __shared__ float sBias[128];

    const int tid  = threadIdx.x;
    const int lane = tid & 31;
    const int g = lane >> 2, t = lane & 3;
    const size_t b0w = (size_t)blockIdx.x * NT + (size_t)(tid >> 5) * 32;

    // ---- one-time weight pack (identical to verified round-5 layout) ----
    // idx = (((m*2+kt)*4+nt)*32+lane)*4 + s ; s: 0=b0hi 1=b1hi 2=b0lo 3=b1lo
    for (int idx = tid; idx < 7*1024; idx += NT){
        int s  = idx & 3;
        int ln = (idx >> 2) & 31;
        int nt = (idx >> 7) & 3;
        int kt = (idx >> 9) & 1;
        int m  = idx >> 10;
        int j = nt*8 + (ln >> 2);
        int k = kt*16 + 2*(ln & 3) + (s & 1)*8;
        const float* srcm = (m < 3) ? (W_ih + m*NV*NV)
                          : (m < 6) ? (W_hh + (m-3)*NV*NV)
                                    : W_lin;
        float v0 = (j < NV && k   < NV) ? srcm[j*NV + k]   : 0.0f;
        float v1 = (j < NV && k+1 < NV) ? srcm[j*NV + k+1] : 0.0f;
        __half2 hi = __floats2half2_rn(v0, v1);
        if (s >> 1){
            float2 hf = __half22float2(hi);
            sW[idx] = h2u(__floats2half2_rn(v0 - hf.x, v1 - hf.y));
        } else {
            sW[idx] = h2u(hi);
        }
    }
    {
        int l = tid >> 5, j = tid & 31;
        float v = 0.0f;
        if (j < NV) v = (l < 3) ? (b_ih[l*NV + j] + b_hh[l*NV + j]) : b_lin[j];
        sBias[l*32 + j] = v;
    }
    __syncthreads();
    // ---- warps fully independent; no syncs, no smem state from here ----

    uint32_t ha[NL][2][2][4], la[NL][2][2][4];   // per-layer h as A-fragments (hi/lo)

    // h0 -> fragments (direct gmem, scalar loads, col-31 guarded)
    #pragma unroll
    for (int l = 0; l < NL; l++){
        const float* src = h0 + ((size_t)l * BATCH + b0w) * NV;
        #pragma unroll
        for (int mt = 0; mt < 2; mt++){
            const float* r0p = src + (mt*16 + g) * NV;
            const float* r1p = r0p + 8 * NV;
            #pragma unroll
            for (int kt = 0; kt < 2; kt++){
                int c0 = kt*16 + 2*t, c1 = c0 + 8;
                float e1 = 0.f, f1 = 0.f;
                if (!(kt == 1 && t == 3)){ e1 = r0p[c1+1]; f1 = r1p[c1+1]; }
                split2(r0p[c0], r0p[c0+1], ha[l][mt][kt][0], la[l][mt][kt][0]);
                split2(r1p[c0], r1p[c0+1], ha[l][mt][kt][1], la[l][mt][kt][1]);
                split2(r0p[c1], e1,        ha[l][mt][kt][2], la[l][mt][kt][2]);
                split2(r1p[c1], f1,        ha[l][mt][kt][3], la[l][mt][kt][3]);
            }
        }
    }

    float D[2][4][4];
    const float* xr[2][2];
    #pragma unroll
    for (int mt = 0; mt < 2; mt++){
        xr[mt][0] = inp + (b0w + mt*16 + g) * (TSTEPS*NV);
        xr[mt][1] = xr[mt][0] + 8 * (TSTEPS*NV);
    }

    #pragma unroll 1
    for (int ts = 0; ts < TSTEPS; ts++){
        #pragma unroll
        for (int l = 0; l < NL; l++){
            // init D from combined bias
            #pragma unroll
            for (int nt = 0; nt < 4; nt++){
                float bA = sBias[l*32 + nt*8 + 2*t];
                float bB = sBias[l*32 + nt*8 + 2*t + 1];
                D[0][nt][0] = bA; D[0][nt][1] = bB; D[0][nt][2] = bA; D[0][nt][3] = bB;
                D[1][nt][0] = bA; D[1][nt][1] = bB; D[1][nt][2] = bA; D[1][nt][3] = bB;
            }
            // input accumulation
            if (l == 0){
                const uint32_t* wm = sW;   // W_ih layer 0
                #pragma unroll
                for (int kt = 0; kt < 2; kt++){
                    uint4 wv[4];
                    #pragma unroll
                    for (int nt = 0; nt < 4; nt++)
                        wv[nt] = ((const uint4*)wm)[(kt*4 + nt)*32 + lane];
                    #pragma unroll
                    for (int mt = 0; mt < 2; mt++){
                        const float* rp = xr[mt][0] + ts*NV;
                        const float* rq = xr[mt][1] + ts*NV;
                        int c0 = kt*16 + 2*t, c1 = c0 + 8;
                        float e1 = 0.f, f1 = 0.f;
                        if (!(kt == 1 && t == 3)){ e1 = rp[c1+1]; f1 = rq[c1+1]; }
                        uint32_t xa[4], xl[4];
                        split2(rp[c0], rp[c0+1], xa[0], xl[0]);
                        split2(rq[c0], rq[c0+1], xa[1], xl[1]);
                        split2(rp[c1], e1,       xa[2], xl[2]);
                        split2(rq[c1], f1,       xa[3], xl[3]);
                        #pragma unroll
                        for (int nt = 0; nt < 4; nt++){
                            mma_f16(D[mt][nt], xa[0],xa[1],xa[2],xa[3], wv[nt].x, wv[nt].y);
                            mma_f16(D[mt][nt], xa[0],xa[1],xa[2],xa[3], wv[nt].z, wv[nt].w);
                            mma_f16(D[mt][nt], xl[0],xl[1],xl[2],xl[3], wv[nt].x, wv[nt].y);
                        }
                    }
                }
            } else {
                accum_frag(D, ha[l-1], la[l-1], sW + l*1024, lane);
            }
            // recurrent accumulation
            accum_frag(D, ha[l], la[l], sW + (3+l)*1024, lane);

            // epilogue: tanh -> next A-fragments, all in registers
            #pragma unroll
            for (int mt = 0; mt < 2; mt++)
                #pragma unroll
                for (int kt = 0; kt < 2; kt++){
                    float v0 = fast_tanh(D[mt][2*kt][0]);
                    float v1 = fast_tanh(D[mt][2*kt][1]);
                    float v2 = fast_tanh(D[mt][2*kt][2]);
                    float v3 = fast_tanh(D[mt][2*kt][3]);
                    float w0 = fast_tanh(D[mt][2*kt+1][0]);
                    float w1 = fast_tanh(D[mt][2*kt+1][1]);
                    float w2 = fast_tanh(D[mt][2*kt+1][2]);
                    float w3 = fast_tanh(D[mt][2*kt+1][3]);
                    split2(v0, v1, ha[l][mt][kt][0], la[l][mt][kt][0]);
                    split2(v2, v3, ha[l][mt][kt][1], la[l][mt][kt][1]);
                    split2(w0, w1, ha[l][mt][kt][2], la[l][mt][kt][2]);
                    split2(w2, w3, ha[l][mt][kt][3], la[l][mt][kt][3]);
                }
        }
    }

    // ---- final linear + tanh ----
    #pragma unroll
    for (int nt = 0; nt < 4; nt++){
        float bA = sBias[3*32 + nt*8 + 2*t];
        float bB = sBias[3*32 + nt*8 + 2*t + 1];
        D[0][nt][0] = bA; D[0][nt][1] = bB; D[0][nt][2] = bA; D[0][nt][3] = bB;
        D[1][nt][0] = bA; D[1][nt][1] = bB; D[1][nt][2] = bA; D[1][nt][3] = bB;
    }
    accum_frag(D, ha[2], la[2], sW + 6*1024, lane);
    #pragma unroll
    for (int mt = 0; mt < 2; mt++)
        #pragma unroll
        for (int nt = 0; nt < 4; nt++)
            #pragma unroll
            for (int i = 0; i < 4; i++)
                D[mt][nt][i] = fast_tanh(D[mt][nt][i]);
    if (t == 3){ D[0][3][1] = -3.0e38f; D[0][3][3] = -3.0e38f;
                 D[1][3][1] = -3.0e38f; D[1][3][3] = -3.0e38f; }

    // ---- softmax per row (across quad lanes) + direct store ----
    #pragma unroll
    for (int mt = 0; mt < 2; mt++)
        #pragma unroll
        for (int hh = 0; hh < 2; hh++){
            float m = -3.0e38f;
            #pragma unroll
            for (int nt = 0; nt < 4; nt++)
                m = fmaxf(m, fmaxf(D[mt][nt][2*hh], D[mt][nt][2*hh+1]));
            m = fmaxf(m, __shfl_xor_sync(0xffffffffu, m, 1));
            m = fmaxf(m, __shfl_xor_sync(0xffffffffu, m, 2));
            float s = 0.0f;
            #pragma unroll
            for (int nt = 0; nt < 4; nt++){
                float e0 = __expf(D[mt][nt][2*hh]   - m);
                float e1 = __expf(D[mt][nt][2*hh+1] - m);
                D[mt][nt][2*hh] = e0; D[mt][nt][2*hh+1] = e1;
                s += e0 + e1;
            }
            s += __shfl_xor_sync(0xffffffffu, s, 1);
            s += __shfl_xor_sync(0xffffffffu, s, 2);
            float inv = __fdividef(1.0f, s);
            size_t ro = (b0w + mt*16 + g + 8*hh) * (size_t)NV;
            #pragma unroll
            for (int nt = 0; nt < 4; nt++){
                int c = nt*8 + 2*t;
                out[ro + c] = D[mt][nt][2*hh] * inv;
                if (c + 1 < NV) out[ro + c + 1] = D[mt][nt][2*hh+1] * inv;
            }
        }
}

extern "C" void kernel_launch(void* const* d_in, const int* in_sizes, int n_in,
                              void* d_out, int out_size)
{
    const float* inp   = (const float*)d_in[0];
    const float* h0    = (const float*)d_in[1];
    const float* W_ih  = (const float*)d_in[2];
    const float* W_hh  = (const float*)d_in[3];
    const float* b_ih  = (const float*)d_in[4];
    const float* b_hh  = (const float*)d_in[5];
    const float* W_lin = (const float*)d_in[6];
    const float* b_lin = (const float*)d_in[7];
    float* out = (float*)d_out;

    rnn_reg<<<BATCH / NT, NT>>>(inp, h0, W_ih, W_hh, b_ih, b_hh, W_lin, b_lin, out);
}

// round 11
// speedup vs baseline: 3.0509x; 1.1127x over previous
#include <cuda_runtime.h>
#include <cuda_fp16.h>
#include <cstdint>

#define BATCH  131072
#define TSTEPS 6
#define NV     31
#define NL     3
#define NT     128
#define ROWS_PER_WARP 16
#define ROWS_PER_CTA  64   // 4 warps * 16

__device__ __forceinline__ void mma_f16(float* D, uint32_t a0, uint32_t a1,
                                        uint32_t a2, uint32_t a3,
                                        uint32_t b0, uint32_t b1){
    asm volatile("mma.sync.aligned.m16n8k16.row.col.f32.f16.f16.f32 "
                 "{%0,%1,%2,%3}, {%4,%5,%6,%7}, {%8,%9}, {%0,%1,%2,%3};"
                 : "+f"(D[0]), "+f"(D[1]), "+f"(D[2]), "+f"(D[3])
                 : "r"(a0), "r"(a1), "r"(a2), "r"(a3), "r"(b0), "r"(b1));
}
__device__ __forceinline__ float fast_tanh(float x){
    float e = __expf(2.0f * x);
    return 1.0f - __fdividef(2.0f, e + 1.0f);
}
__device__ __forceinline__ uint32_t h2u(__half2 h){ return *(uint32_t*)&h; }
// pack (x,y) -> hi f16x2 and residual lo f16x2
__device__ __forceinline__ void split2(float x, float y, uint32_t& hi, uint32_t& lo){
    __half2 h = __floats2half2_rn(x, y);
    float2 f = __half22float2(h);
    hi = h2u(h);
    lo = h2u(__floats2half2_rn(x - f.x, y - f.y));
}

// D[4][4] += A(frags, M=16) x W^T, 3-product f16 split, B from shared
__device__ __forceinline__ void accum_frag(float D[4][4],
                                           const uint32_t (&A)[2][4],
                                           const uint32_t (&L)[2][4],
                                           const uint32_t* __restrict__ wm, int lane){
    #pragma unroll
    for (int kt = 0; kt < 2; kt++){
        uint4 wv[4];
        #pragma unroll
        for (int nt = 0; nt < 4; nt++)
            wv[nt] = ((const uint4*)wm)[(kt*4 + nt)*32 + lane];
        #pragma unroll
        for (int nt = 0; nt < 4; nt++){
            mma_f16(D[nt], A[kt][0], A[kt][1], A[kt][2], A[kt][3], wv[nt].x, wv[nt].y);
            mma_f16(D[nt], A[kt][0], A[kt][1], A[kt][2], A[kt][3], wv[nt].z, wv[nt].w);
            mma_f16(D[nt], L[kt][0], L[kt][1], L[kt][2], L[kt][3], wv[nt].x, wv[nt].y);
        }
    }
}

__global__ void __launch_bounds__(NT, 4)
rnn_reg16(const float* __restrict__ inp,  const float* __restrict__ h0,
          const float* __restrict__ W_ih, const float* __restrict__ W_hh,
          const float* __restrict__ b_ih, const float* __restrict__ b_hh,
          const float* __restrict__ W_lin,const float* __restrict__ b_lin,
          float* __restrict__ out)
{
    __shared__ __align__(16) uint32_t sW[7*1024];   // 7 matrices, B-frag order, f16 hi/lo
    __shared__ float sBias[128];

    const int tid  = threadIdx.x;
    const int lane = tid & 31;
    const int g = lane >> 2, t = lane & 3;
    const size_t b0w = (size_t)blockIdx.x * ROWS_PER_CTA + (size_t)(tid >> 5) * ROWS_PER_WARP;

    // ---- one-time weight pack (verified layout from rounds 5-7) ----
    // idx = (((m*2+kt)*4+nt)*32+lane)*4 + s ; s: 0=b0hi 1=b1hi 2=b0lo 3=b1lo
    for (int idx = tid; idx < 7*1024; idx += NT){
        int s  = idx & 3;
        int ln = (idx >> 2) & 31;
        int nt = (idx >> 7) & 3;
        int kt = (idx >> 9) & 1;
        int m  = idx >> 10;
        int j = nt*8 + (ln >> 2);
        int k = kt*16 + 2*(ln & 3) + (s & 1)*8;
        const float* srcm = (m < 3) ? (W_ih + m*NV*NV)
                          : (m < 6) ? (W_hh + (m-3)*NV*NV)
                                    : W_lin;
        float v0 = (j < NV && k   < NV) ? srcm[j*NV + k]   : 0.0f;
        float v1 = (j < NV && k+1 < NV) ? srcm[j*NV + k+1] : 0.0f;
        __half2 hi = __floats2half2_rn(v0, v1);
        if (s >> 1){
            float2 hf = __half22float2(hi);
            sW[idx] = h2u(__floats2half2_rn(v0 - hf.x, v1 - hf.y));
        } else {
            sW[idx] = h2u(hi);
        }
    }
    {
        int l = tid >> 5, j = tid & 31;
        float v = 0.0f;
        if (j < NV) v = (l < 3) ? (b_ih[l*NV + j] + b_hh[l*NV + j]) : b_lin[j];
        sBias[l*32 + j] = v;
    }
    __syncthreads();
    // ---- warps fully independent; no syncs, no smem state from here ----

    uint32_t ha[NL][2][4], la[NL][2][4];   // per-layer h as A-fragments (hi/lo), M=16

    // h0 -> fragments (direct gmem, scalar loads, col-31 guarded)
    #pragma unroll
    for (int l = 0; l < NL; l++){
        const float* src = h0 + ((size_t)l * BATCH + b0w) * NV;
        const float* r0p = src + g * NV;
        const float* r1p = r0p + 8 * NV;
        #pragma unroll
        for (int kt = 0; kt < 2; kt++){
            int c0 = kt*16 + 2*t, c1 = c0 + 8;
            float e1 = 0.f, f1 = 0.f;
            if (!(kt == 1 && t == 3)){ e1 = r0p[c1+1]; f1 = r1p[c1+1]; }
            split2(r0p[c0], r0p[c0+1], ha[l][kt][0], la[l][kt][0]);
            split2(r1p[c0], r1p[c0+1], ha[l][kt][1], la[l][kt][1]);
            split2(r0p[c1], e1,        ha[l][kt][2], la[l][kt][2]);
            split2(r1p[c1], f1,        ha[l][kt][3], la[l][kt][3]);
        }
    }

    float D[4][4];

    #pragma unroll 1
    for (int ts = 0; ts < TSTEPS; ts++){
        #pragma unroll
        for (int l = 0; l < NL; l++){
            // init D from combined bias
            #pragma unroll
            for (int nt = 0; nt < 4; nt++){
                float bA = sBias[l*32 + nt*8 + 2*t];
                float bB = sBias[l*32 + nt*8 + 2*t + 1];
                D[nt][0] = bA; D[nt][1] = bB; D[nt][2] = bA; D[nt][3] = bB;
            }
            // input accumulation
            if (l == 0){
                const float* rp = inp + (b0w + g) * (TSTEPS*NV) + ts*NV;
                const float* rq = rp + 8 * (TSTEPS*NV);
                #pragma unroll
                for (int kt = 0; kt < 2; kt++){
                    uint4 wv[4];
                    #pragma unroll
                    for (int nt = 0; nt < 4; nt++)
                        wv[nt] = ((const uint4*)sW)[(kt*4 + nt)*32 + lane];
                    int c0 = kt*16 + 2*t, c1 = c0 + 8;
                    float e1 = 0.f, f1 = 0.f;
                    if (!(kt == 1 && t == 3)){ e1 = rp[c1+1]; f1 = rq[c1+1]; }
                    uint32_t xa[4], xl[4];
                    split2(rp[c0], rp[c0+1], xa[0], xl[0]);
                    split2(rq[c0], rq[c0+1], xa[1], xl[1]);
                    split2(rp[c1], e1,       xa[2], xl[2]);
                    split2(rq[c1], f1,       xa[3], xl[3]);
                    #pragma unroll
                    for (int nt = 0; nt < 4; nt++){
                        mma_f16(D[nt], xa[0],xa[1],xa[2],xa[3], wv[nt].x, wv[nt].y);
                        mma_f16(D[nt], xa[0],xa[1],xa[2],xa[3], wv[nt].z, wv[nt].w);
                        mma_f16(D[nt], xl[0],xl[1],xl[2],xl[3], wv[nt].x, wv[nt].y);
                    }
                }
            } else {
                accum_frag(D, ha[l-1], la[l-1], sW + l*1024, lane);
            }
            // recurrent accumulation
            accum_frag(D, ha[l], la[l], sW + (3+l)*1024, lane);

            // epilogue: tanh -> next A-fragments, all in registers
            #pragma unroll
            for (int kt = 0; kt < 2; kt++){
                float v0 = fast_tanh(D[2*kt][0]);
                float v1 = fast_tanh(D[2*kt][1]);
                float v2 = fast_tanh(D[2*kt][2]);
                float v3 = fast_tanh(D[2*kt][3]);
                float w0 = fast_tanh(D[2*kt+1][0]);
                float w1 = fast_tanh(D[2*kt+1][1]);
                float w2 = fast_tanh(D[2*kt+1][2]);
                float w3 = fast_tanh(D[2*kt+1][3]);
                split2(v0, v1, ha[l][kt][0], la[l][kt][0]);
                split2(v2, v3, ha[l][kt][1], la[l][kt][1]);
                split2(w0, w1, ha[l][kt][2], la[l][kt][2]);
                split2(w2, w3, ha[l][kt][3], la[l][kt][3]);
            }
        }
    }

    // ---- final linear + tanh ----
    #pragma unroll
    for (int nt = 0; nt < 4; nt++){
        float bA = sBias[3*32 + nt*8 + 2*t];
        float bB = sBias[3*32 + nt*8 + 2*t + 1];
        D[nt][0] = bA; D[nt][1] = bB; D[nt][2] = bA; D[nt][3] = bB;
    }
    accum_frag(D, ha[2], la[2], sW + 6*1024, lane);
    #pragma unroll
    for (int nt = 0; nt < 4; nt++)
        #pragma unroll
        for (int i = 0; i < 4; i++)
            D[nt][i] = fast_tanh(D[nt][i]);
    if (t == 3){ D[3][1] = -3.0e38f; D[3][3] = -3.0e38f; }

    // ---- softmax per row (across quad lanes) + direct store ----
    #pragma unroll
    for (int hh = 0; hh < 2; hh++){
        float m = -3.0e38f;
        #pragma unroll
        for (int nt = 0; nt < 4; nt++)
            m = fmaxf(m, fmaxf(D[nt][2*hh], D[nt][2*hh+1]));
        m = fmaxf(m, __shfl_xor_sync(0xffffffffu, m, 1));
        m = fmaxf(m, __shfl_xor_sync(0xffffffffu, m, 2));
        float s = 0.0f;
        #pragma unroll
        for (int nt = 0; nt < 4; nt++){
            float e0 = __expf(D[nt][2*hh]   - m);
            float e1 = __expf(D[nt][2*hh+1] - m);
            D[nt][2*hh] = e0; D[nt][2*hh+1] = e1;
            s += e0 + e1;
        }
        s += __shfl_xor_sync(0xffffffffu, s, 1);
        s += __shfl_xor_sync(0xffffffffu, s, 2);
        float inv = __fdividef(1.0f, s);
        size_t ro = (b0w + g + 8*hh) * (size_t)NV;
        #pragma unroll
        for (int nt = 0; nt < 4; nt++){
            int c = nt*8 + 2*t;
            out[ro + c] = D[nt][2*hh] * inv;
            if (c + 1 < NV) out[ro + c + 1] = D[nt][2*hh+1] * inv;
        }
    }
}

extern "C" void kernel_launch(void* const* d_in, const int* in_sizes, int n_in,
                              void* d_out, int out_size)
{
    const float* inp   = (const float*)d_in[0];
    const float* h0    = (const float*)d_in[1];
    const float* W_ih  = (const float*)d_in[2];
    const float* W_hh  = (const float*)d_in[3];
    const float* b_ih  = (const float*)d_in[4];
    const float* b_hh  = (const float*)d_in[5];
    const float* W_lin = (const float*)d_in[6];
    const float* b_lin = (const float*)d_in[7];
    float* out = (float*)d_out;

    rnn_reg16<<<BATCH / ROWS_PER_CTA, NT>>>(inp, h0, W_ih, W_hh, b_ih, b_hh,
                                            W_lin, b_lin, out);
}

// round 13
// speedup vs baseline: 3.7869x; 1.2412x over previous
#include <cuda_runtime.h>
#include <cuda_fp16.h>
#include <cstdint>

#define BATCH  131072
#define TSTEPS 6
#define NV     31
#define NL     3
#define NT     128
#define ROWS_PER_WARP 16
#define ROWS_PER_CTA  64   // 4 warps * 16

__device__ __forceinline__ void mma_f16(float* D, uint32_t a0, uint32_t a1,
                                        uint32_t a2, uint32_t a3,
                                        uint32_t b0, uint32_t b1){
    asm volatile("mma.sync.aligned.m16n8k16.row.col.f32.f16.f16.f32 "
                 "{%0,%1,%2,%3}, {%4,%5,%6,%7}, {%8,%9}, {%0,%1,%2,%3};"
                 : "+f"(D[0]), "+f"(D[1]), "+f"(D[2]), "+f"(D[3])
                 : "r"(a0), "r"(a1), "r"(a2), "r"(a3), "r"(b0), "r"(b1));
}
__device__ __forceinline__ float fast_tanh(float x){
    float e = __expf(2.0f * x);
    return 1.0f - __fdividef(2.0f, e + 1.0f);
}
__device__ __forceinline__ uint32_t h2u(__half2 h){ return *(uint32_t*)&h; }
__device__ __forceinline__ uint32_t pack2(float x, float y){
    return h2u(__floats2half2_rn(x, y));
}

// D[4][4] += A(frags, M=16, f16 hi only) x W^T (exact W = Whi + Wlo), 2-product
__device__ __forceinline__ void accum_frag(float D[4][4],
                                           const uint32_t (&A)[2][4],
                                           const uint32_t* __restrict__ wm, int lane){
    #pragma unroll
    for (int kt = 0; kt < 2; kt++){
        uint4 wv[4];
        #pragma unroll
        for (int nt = 0; nt < 4; nt++)
            wv[nt] = ((const uint4*)wm)[(kt*4 + nt)*32 + lane];
        #pragma unroll
        for (int nt = 0; nt < 4; nt++){
            mma_f16(D[nt], A[kt][0], A[kt][1], A[kt][2], A[kt][3], wv[nt].x, wv[nt].y);
            mma_f16(D[nt], A[kt][0], A[kt][1], A[kt][2], A[kt][3], wv[nt].z, wv[nt].w);
        }
    }
}

__global__ void __launch_bounds__(NT, 5)
rnn_reg2p(const float* __restrict__ inp,  const float* __restrict__ h0,
          const float* __restrict__ W_ih, const float* __restrict__ W_hh,
          const float* __restrict__ b_ih, const float* __restrict__ b_hh,
          const float* __restrict__ W_lin,const float* __restrict__ b_lin,
          float* __restrict__ out)
{
    __shared__ __align__(16) uint32_t sW[7*1024];   // 7 matrices, B-frag order, f16 hi/lo
    __shared__ float sBias[128];

    const int tid  = threadIdx.x;
    const int lane = tid & 31;
    const int g = lane >> 2, t = lane & 3;
    const size_t b0w = (size_t)blockIdx.x * ROWS_PER_CTA + (size_t)(tid >> 5) * ROWS_PER_WARP;

    // ---- one-time weight pack (verified layout from rounds 5-11) ----
    // idx = (((m*2+kt)*4+nt)*32+lane)*4 + s ; s: 0=b0hi 1=b1hi 2=b0lo 3=b1lo
    for (int idx = tid; idx < 7*1024; idx += NT){
        int s  = idx & 3;
        int ln = (idx >> 2) & 31;
        int nt = (idx >> 7) & 3;
        int kt = (idx >> 9) & 1;
        int m  = idx >> 10;
        int j = nt*8 + (ln >> 2);
        int k = kt*16 + 2*(ln & 3) + (s & 1)*8;
        const float* srcm = (m < 3) ? (W_ih + m*NV*NV)
                          : (m < 6) ? (W_hh + (m-3)*NV*NV)
                                    : W_lin;
        float v0 = (j < NV && k   < NV) ? srcm[j*NV + k]   : 0.0f;
        float v1 = (j < NV && k+1 < NV) ? srcm[j*NV + k+1] : 0.0f;
        __half2 hi = __floats2half2_rn(v0, v1);
        if (s >> 1){
            float2 hf = __half22float2(hi);
            sW[idx] = h2u(__floats2half2_rn(v0 - hf.x, v1 - hf.y));
        } else {
            sW[idx] = h2u(hi);
        }
    }
    {
        int l = tid >> 5, j = tid & 31;
        float v = 0.0f;
        if (j < NV) v = (l < 3) ? (b_ih[l*NV + j] + b_hh[l*NV + j]) : b_lin[j];
        sBias[l*32 + j] = v;
    }
    __syncthreads();
    // ---- warps fully independent; no syncs, no smem state from here ----

    uint32_t ha[NL][2][4];   // per-layer h as A-fragments (f16 hi), M=16

    // h0 -> fragments (direct gmem, scalar loads, col-31 guarded)
    #pragma unroll
    for (int l = 0; l < NL; l++){
        const float* src = h0 + ((size_t)l * BATCH + b0w) * NV;
        const float* r0p = src + g * NV;
        const float* r1p = r0p + 8 * NV;
        #pragma unroll
        for (int kt = 0; kt < 2; kt++){
            int c0 = kt*16 + 2*t, c1 = c0 + 8;
            float e1 = 0.f, f1 = 0.f;
            if (!(kt == 1 && t == 3)){ e1 = r0p[c1+1]; f1 = r1p[c1+1]; }
            ha[l][kt][0] = pack2(r0p[c0], r0p[c0+1]);
            ha[l][kt][1] = pack2(r1p[c0], r1p[c0+1]);
            ha[l][kt][2] = pack2(r0p[c1], e1);
            ha[l][kt][3] = pack2(r1p[c1], f1);
        }
    }

    float D[4][4];

    #pragma unroll 1
    for (int ts = 0; ts < TSTEPS; ts++){
        #pragma unroll
        for (int l = 0; l < NL; l++){
            // init D from combined bias
            #pragma unroll
            for (int nt = 0; nt < 4; nt++){
                float bA = sBias[l*32 + nt*8 + 2*t];
                float bB = sBias[l*32 + nt*8 + 2*t + 1];
                D[nt][0] = bA; D[nt][1] = bB; D[nt][2] = bA; D[nt][3] = bB;
            }
            // input accumulation
            if (l == 0){
                const float* rp = inp + (b0w + g) * (TSTEPS*NV) + ts*NV;
                const float* rq = rp + 8 * (TSTEPS*NV);
                uint32_t xa[2][4];
                #pragma unroll
                for (int kt = 0; kt < 2; kt++){
                    int c0 = kt*16 + 2*t, c1 = c0 + 8;
                    float e1 = 0.f, f1 = 0.f;
                    if (!(kt == 1 && t == 3)){ e1 = rp[c1+1]; f1 = rq[c1+1]; }
                    xa[kt][0] = pack2(rp[c0], rp[c0+1]);
                    xa[kt][1] = pack2(rq[c0], rq[c0+1]);
                    xa[kt][2] = pack2(rp[c1], e1);
                    xa[kt][3] = pack2(rq[c1], f1);
                }
                accum_frag(D, xa, sW, lane);
            } else {
                accum_frag(D, ha[l-1], sW + l*1024, lane);
            }
            // recurrent accumulation
            accum_frag(D, ha[l], sW + (3+l)*1024, lane);

            // epilogue: tanh -> next A-fragments, all in registers
            #pragma unroll
            for (int kt = 0; kt < 2; kt++){
                ha[l][kt][0] = pack2(fast_tanh(D[2*kt][0]),   fast_tanh(D[2*kt][1]));
                ha[l][kt][1] = pack2(fast_tanh(D[2*kt][2]),   fast_tanh(D[2*kt][3]));
                ha[l][kt][2] = pack2(fast_tanh(D[2*kt+1][0]), fast_tanh(D[2*kt+1][1]));
                ha[l][kt][3] = pack2(fast_tanh(D[2*kt+1][2]), fast_tanh(D[2*kt+1][3]));
            }
        }
    }

    // ---- final linear + tanh ----
    #pragma unroll
    for (int nt = 0; nt < 4; nt++){
        float bA = sBias[3*32 + nt*8 + 2*t];
        float bB = sBias[3*32 + nt*8 + 2*t + 1];
        D[nt][0] = bA; D[nt][1] = bB; D[nt][2] = bA; D[nt][3] = bB;
    }
    accum_frag(D, ha[2], sW + 6*1024, lane);
    #pragma unroll
    for (int nt = 0; nt < 4; nt++)
        #pragma unroll
        for (int i = 0; i < 4; i++)
            D[nt][i] = fast_tanh(D[nt][i]);
    if (t == 3){ D[3][1] = -3.0e38f; D[3][3] = -3.0e38f; }

    // ---- softmax per row (across quad lanes) + direct store ----
    #pragma unroll
    for (int hh = 0; hh < 2; hh++){
        float m = -3.0e38f;
        #pragma unroll
        for (int nt = 0; nt < 4; nt++)
            m = fmaxf(m, fmaxf(D[nt][2*hh], D[nt][2*hh+1]));
        m = fmaxf(m, __shfl_xor_sync(0xffffffffu, m, 1));
        m = fmaxf(m, __shfl_xor_sync(0xffffffffu, m, 2));
        float s = 0.0f;
        #pragma unroll
        for (int nt = 0; nt < 4; nt++){
            float e0 = __expf(D[nt][2*hh]   - m);
            float e1 = __expf(D[nt][2*hh+1] - m);
            D[nt][2*hh] = e0; D[nt][2*hh+1] = e1;
            s += e0 + e1;
        }
        s += __shfl_xor_sync(0xffffffffu, s, 1);
        s += __shfl_xor_sync(0xffffffffu, s, 2);
        float inv = __fdividef(1.0f, s);
        size_t ro = (b0w + g + 8*hh) * (size_t)NV;
        #pragma unroll
        for (int nt = 0; nt < 4; nt++){
            int c = nt*8 + 2*t;
            out[ro + c] = D[nt][2*hh] * inv;
            if (c + 1 < NV) out[ro + c + 1] = D[nt][2*hh+1] * inv;
        }
    }
}

extern "C" void kernel_launch(void* const* d_in, const int* in_sizes, int n_in,
                              void* d_out, int out_size)
{
    const float* inp   = (const float*)d_in[0];
    const float* h0    = (const float*)d_in[1];
    const float* W_ih  = (const float*)d_in[2];
    const float* W_hh  = (const float*)d_in[3];
    const float* b_ih  = (const float*)d_in[4];
    const float* b_hh  = (const float*)d_in[5];
    const float* W_lin = (const float*)d_in[6];
    const float* b_lin = (const float*)d_in[7];
    float* out = (float*)d_out;

    rnn_reg2p<<<BATCH / ROWS_PER_CTA, NT>>>(inp, h0, W_ih, W_hh, b_ih, b_hh,
                                            W_lin, b_lin, out);
}